// round 16
// baseline (speedup 1.0000x reference)
#include <cuda_runtime.h>

// DDK_77644418777653 — per-row recurrence scan, dual-stream interleaved
// SMEM staging (two independent 128-row blocks per CTA).
//
// out[:,0] = 1 ; out[:,k] = out[:,k-1] + alpha/out[:,k-1] - beta*in[:,k-1]
// M = 262144 rows, N = 512 cols, fp32, row-major.
//
// Each CTA owns TWO independent 128-row blocks (A, B) with separate smem
// buffers. Steps alternate streams; while stream s computes tile t, the
// other stream's 8 LDG.128 are in flight (issued one step earlier), so the
// CTA's DRAM read stream never goes idle during the serial-divide phase.
// This is the guaranteed-overlap version of what R7/R8/R12 attempted,
// minus their failure modes: independent streams (no recurrence coupling),
// plain LDG.128 (no cp.async alignment or 8-cyc issue floor), TK=32 maps
// (verified conflict-free; TK=16 float4 maps are provably 2-way conflicted).
//
// Schedule (2NT steps, s = step&1, t = step>>1):
//   compute s[t] from sm[s]                  (pf for other stream in flight)
//   __syncthreads
//   store s[t]  (STG.128 from sm[s])
//   STS pf -> sm[1-s]    (stages other stream's pending tile)  [step+1<2NT]
//   pf = LDG own stream's tile t+1                             [step+2<2NT]
//   __syncthreads
// 2 barriers per tile (vs 3 in R15).
//
// Bank maps (TK=32, verified): staging warp = 4 rows x 8 float4-slots,
// bank = (r + 4c) mod 32 -> all 32 banks; compute stride 33 (odd) -> all 32.
//
// fp semantics bit-exact vs XLA:GPU lowering (rel_err=0.0 since R6 — do NOT
// change):  u = add.rn(w, div.rn(a,w));  w' = ffma.rn(-b, x, u)

#define ROWS   128
#define TK     32
#define LDSR   33
#define NCOLS  512
#define NT     (NCOLS / TK)                  // 16 tiles per stream
#define N4     (NCOLS / 4)
#define LD_IT  ((ROWS * TK / 4) / ROWS)      // 8 float4 slots per thread

__global__ __launch_bounds__(ROWS, 6)
void DDK_77644418777653_kernel(const float* __restrict__ in,
                               const float* __restrict__ alpha,
                               const float* __restrict__ beta,
                               float* __restrict__ out) {
    __shared__ float sm[2][ROWS * LDSR];     // 2 x 16896 B = 33792 B

    const int tid = threadIdx.x;
    // CTA b owns row blocks 2b (stream A) and 2b+1 (stream B)
    const int rowA = blockIdx.x * (2 * ROWS);
    const int rowB = rowA + ROWS;

    const float a = alpha[0];
    const float b = beta[0];

    const float4* in4  = reinterpret_cast<const float4*>(in);
    float4*       out4 = reinterpret_cast<float4*>(out);

    // Staging slots: idx = it*ROWS + tid, r = idx>>3, c4 = idx&7.
    // Recompute per use (cheap shifts) to save registers vs caching arrays.

    // ---- prologue: stage A tile0 into sm[0]; leave B tile0 in flight ----
    float4 pf[LD_IT];
    #pragma unroll
    for (int it = 0; it < LD_IT; ++it) {
        int idx = it * ROWS + tid;
        pf[it] = in4[(size_t)(rowA + (idx >> 3)) * N4 + (idx & 7)];
    }
    #pragma unroll
    for (int it = 0; it < LD_IT; ++it) {
        int idx = it * ROWS + tid;
        float* d = &sm[0][(idx >> 3) * LDSR + (idx & 7) * 4];
        d[0] = pf[it].x; d[1] = pf[it].y; d[2] = pf[it].z; d[3] = pf[it].w;
    }
    #pragma unroll
    for (int it = 0; it < LD_IT; ++it) {
        int idx = it * ROWS + tid;
        pf[it] = in4[(size_t)(rowB + (idx >> 3)) * N4 + (idx & 7)];
    }
    __syncthreads();

    float wA = 1.0f, xpA = 0.0f;   // stream A recurrence state
    float wB = 1.0f, xpB = 0.0f;   // stream B recurrence state
    bool  firstA = true, firstB = true;

    for (int step = 0; step < 2 * NT; ++step) {
        const int  s    = step & 1;           // 0 = A, 1 = B
        const int  t    = step >> 1;
        const int  kc4  = t * (TK / 4);
        const int  row0 = s ? rowB : rowA;
        float*     cur  = sm[s];

        // ---- compute stream s, tile t (other stream's LDGs in flight) ----
        {
            float  w     = s ? wB : wA;
            float  xprev = s ? xpB : xpA;
            bool   first = s ? firstB : firstA;
            float* mrow  = &cur[tid * LDSR];
            #pragma unroll
            for (int i = 0; i < TK; ++i) {
                float x = mrow[i];   // input col t*TK+i (read before overwrite)
                float u  = __fadd_rn(w, __fdiv_rn(a, w));
                float wn = __fmaf_rn(-b, xprev, u);
                w = first ? 1.0f : wn;
                mrow[i] = w;
                xprev   = x;
                first   = false;
            }
            if (s) { wB = w; xpB = xprev; firstB = false; }
            else   { wA = w; xpA = xprev; firstA = false; }
        }
        __syncthreads();   // compute writes visible for cross-row store

        // ---- store stream s, tile t ----
        #pragma unroll
        for (int it = 0; it < LD_IT; ++it) {
            int idx = it * ROWS + tid;
            const float* sp = &cur[(idx >> 3) * LDSR + (idx & 7) * 4];
            out4[(size_t)(row0 + (idx >> 3)) * N4 + kc4 + (idx & 7)] =
                make_float4(sp[0], sp[1], sp[2], sp[3]);
        }

        // ---- stage pf (other stream's pending tile) into sm[1-s] ----
        // sm[1-s] last read two syncs ago (its compute+store finished).
        if (step + 1 < 2 * NT) {
            float* nxt = sm[1 - s];
            #pragma unroll
            for (int it = 0; it < LD_IT; ++it) {
                int idx = it * ROWS + tid;
                float* d = &nxt[(idx >> 3) * LDSR + (idx & 7) * 4];
                d[0] = pf[it].x; d[1] = pf[it].y;
                d[2] = pf[it].z; d[3] = pf[it].w;
            }
        }

        // ---- prefetch own stream's next tile (in flight through the next
        //      step's compute of the other stream) ----
        if (step + 2 < 2 * NT) {
            const int kn4 = (t + 1) * (TK / 4);
            #pragma unroll
            for (int it = 0; it < LD_IT; ++it) {
                int idx = it * ROWS + tid;
                pf[it] = in4[(size_t)(row0 + (idx >> 3)) * N4 + kn4 + (idx & 7)];
            }
        }
        __syncthreads();   // staged tile visible; store reads of cur done
    }
}

extern "C" void kernel_launch(void* const* d_in, const int* in_sizes, int n_in,
                              void* d_out, int out_size) {
    const float* in    = (const float*)d_in[0];   // [262144, 512] fp32
    const float* alpha = (const float*)d_in[1];   // [1]
    const float* beta  = (const float*)d_in[2];   // [1]
    float*       out   = (float*)d_out;           // [262144, 512] fp32

    const int M = in_sizes[0] / NCOLS;            // 262144
    DDK_77644418777653_kernel<<<M / (2 * ROWS), ROWS>>>(in, alpha, beta, out);
}

// round 17
// speedup vs baseline: 1.4610x; 1.4610x over previous
#include <cuda_runtime.h>

// DDK_77644418777653 — per-row recurrence scan, transposed-tile SMEM staging.
//
// out[:,0] = 1 ; out[:,k] = out[:,k-1] + alpha/out[:,k-1] - beta*in[:,k-1]
// M = 262144 rows, N = 512 cols, fp32, row-major.
//
// Data path identical to the verified R6/R15 kernel; ROWS 128 -> 64.
// Session evidence (R6..R16): explicit intra-CTA pipelining always loses
// (register pressure + barrier coupling); what wins is many small symmetric
// CTAs staggering their load/compute/store phases statistically. ROWS=64
// gives 8.45 KB smem / 2 warps / ~64 regs per CTA -> 16 CTAs/SM at the same
// 32 warps/SM as R15 (which ran 8 CTAs/SM, DRAM=69.4%): double the number
// of independent phase positions per SM, so the DRAM read+write streams
// stay busy through each CTA's serial-divide phase.
//
// Bank maps (TK=32, verified, ROWS-invariant):
//   staging: warp = 4 rows x 8 float4-slots, bank = (r + 4c) mod 32 -> all 32
//   compute: stride 33 (odd) -> 32 distinct banks
//
// fp semantics bit-exact vs XLA:GPU lowering (rel_err=0.0 since R6 — do NOT
// change):
//   t  = div.rn(a, w)
//   u  = add.rn(w, t)
//   w' = ffma.rn(-b, x, u)

#define ROWS   64
#define TK     32
#define LDSR   33              // padded smem row stride (odd -> conflict-free)
#define NCOLS  512
#define N4     (NCOLS / 4)
#define LD_IT  ((ROWS * TK / 4) / ROWS)   // 8 float4 slots per thread per tile

__global__ __launch_bounds__(ROWS)
void DDK_77644418777653_kernel(const float* __restrict__ in,
                               const float* __restrict__ alpha,
                               const float* __restrict__ beta,
                               float* __restrict__ out) {
    __shared__ float sm[ROWS * LDSR];   // 8448 B

    const int tid  = threadIdx.x;
    const int row0 = blockIdx.x * ROWS;

    const float a = alpha[0];
    const float b = beta[0];

    const float4* in4  = reinterpret_cast<const float4*>(in);
    float4*       out4 = reinterpret_cast<float4*>(out);

    // Staging slots this thread services: idx = it*ROWS + tid,
    // r = idx>>3 (4 consecutive rows per warp), c4 = idx&7.
    int rr[LD_IT], cc[LD_IT];
    #pragma unroll
    for (int it = 0; it < LD_IT; ++it) {
        int idx = it * ROWS + tid;
        rr[it] = idx >> 3;
        cc[it] = idx & 7;
    }

    float w     = 1.0f;   // recurrence state for this thread's row
    float xprev = 0.0f;   // input value carried across tile boundary
    bool  first = true;   // col 0 of the whole row is exactly 1

    for (int t = 0; t < NCOLS / TK; ++t) {
        const int kc4 = t * (TK / 4);

        // ---- coalesced load: 8 LDG.128 front-batched, then STS ----
        {
            float4 pf[LD_IT];
            #pragma unroll
            for (int it = 0; it < LD_IT; ++it)
                pf[it] = in4[(size_t)(row0 + rr[it]) * N4 + kc4 + cc[it]];
            #pragma unroll
            for (int it = 0; it < LD_IT; ++it) {
                float* d = &sm[rr[it] * LDSR + cc[it] * 4];
                d[0] = pf[it].x; d[1] = pf[it].y;
                d[2] = pf[it].z; d[3] = pf[it].w;
            }
        }
        __syncthreads();

        // ---- per-thread serial recurrence over this tile (in-place) ----
        float* mrow = &sm[tid * LDSR];
        #pragma unroll
        for (int i = 0; i < TK; ++i) {
            float x = mrow[i];  // input col t*TK+i (read before overwrite)
            // out col uses input col-1 = xprev. Exact XLA op sequence.
            float u  = __fadd_rn(w, __fdiv_rn(a, w));
            float wn = __fmaf_rn(-b, xprev, u);
            w = first ? 1.0f : wn;
            mrow[i] = w;
            xprev   = x;
            first   = false;     // constant-folds away for i >= 1
        }
        __syncthreads();

        // ---- coalesced store of the tile ----
        #pragma unroll
        for (int it = 0; it < LD_IT; ++it) {
            const float* s = &sm[rr[it] * LDSR + cc[it] * 4];
            out4[(size_t)(row0 + rr[it]) * N4 + kc4 + cc[it]] =
                make_float4(s[0], s[1], s[2], s[3]);
        }
        __syncthreads();   // smem reads done before next tile's STS overwrite
    }
}

extern "C" void kernel_launch(void* const* d_in, const int* in_sizes, int n_in,
                              void* d_out, int out_size) {
    const float* in    = (const float*)d_in[0];   // [262144, 512] fp32
    const float* alpha = (const float*)d_in[1];   // [1]
    const float* beta  = (const float*)d_in[2];   // [1]
    float*       out   = (float*)d_out;           // [262144, 512] fp32

    const int M = in_sizes[0] / NCOLS;            // 262144
    DDK_77644418777653_kernel<<<M / ROWS, ROWS>>>(in, alpha, beta, out);
}